// round 14
// baseline (speedup 1.0000x reference)
#include <cuda_runtime.h>
#include <cuda_fp16.h>
#include <math_constants.h>

// Problem constants (fixed by the reference)
#define NN     20000
#define EE     640000
#define ETOT   (EE + NN)      // edges + self loops
#define INF_C  256
#define HEADS  8
#define HF1    64
#define OUT2   32
#define NEG_SLOPE 0.2f

// ---------------- static scratch (no allocations allowed) ----------------
__device__ __half g_xh  [NN * INF_C];         // x in fp16
__device__ __half g_W1h [INF_C * HEADS * HF1];
__device__ __half g_W2h [HF1 * HEADS * OUT2];
__device__ __half g_h1  [NN * HEADS * HF1];   // layer1 projected features (fp16)
__device__ __half g_hmid[NN * HF1];           // layer1 output (fp16, feeds GEMM2)
__device__ __half g_h2  [NN * HEADS * OUT2];  // layer2 projected features (fp16)
__device__ __align__(16) float g_as1 [NN * HEADS];
__device__ __align__(16) float g_ad1 [NN * HEADS];
__device__ __align__(16) float g_as2 [NN * HEADS];
__device__ __align__(16) float g_ad2 [NN * HEADS];
__device__ int   g_deg [NN];
__device__ int   g_off [NN + 1];
__device__ int   g_cur [NN];
__device__ int   g_csr [ETOT];               // src node of each edge, grouped by dst

// ---------------- conversions (stream 2) ----------------
__device__ __forceinline__ void cvt4(const float* src, __half* dst, int i) {
    float4 v = ((const float4*)src)[i];
    ((half2*)dst)[2 * i]     = __floats2half2_rn(v.x, v.y);
    ((half2*)dst)[2 * i + 1] = __floats2half2_rn(v.z, v.w);
}

__global__ void conv_kernel(const float* __restrict__ x,
                            const float* __restrict__ W1,
                            const float* __restrict__ W2) {
    constexpr int NX  = NN * INF_C / 4;
    constexpr int NW1 = INF_C * HEADS * HF1 / 4;
    constexpr int NW2 = HF1 * HEADS * OUT2 / 4;
    int i = blockIdx.x * blockDim.x + threadIdx.x;
    if (i < NX)                   cvt4(x,  g_xh,  i);
    else if (i < NX + NW1)        cvt4(W1, g_W1h, i - NX);
    else if (i < NX + NW1 + NW2)  cvt4(W2, g_W2h, i - NX - NW1);
}

// ---------------- CSR build (stream 0) ----------------
__global__ void count_deg_kernel(const int* __restrict__ ei) {
    int e = blockIdx.x * blockDim.x + threadIdx.x;
    if (e < EE) atomicAdd(&g_deg[ei[EE + e]], 1);
}

// exclusive scan of (deg + 1 self-loop); places self-loop in slot 0, cursor after it
__global__ void scan_kernel() {
    __shared__ int warpsum[32];
    __shared__ int carry_s;
    const int tid = threadIdx.x, lane = tid & 31, wid = tid >> 5;
    if (tid == 0) carry_s = 0;
    __syncthreads();
    for (int base = 0; base < NN; base += 1024) {
        int i = base + tid;
        int v = (i < NN) ? (g_deg[i] + 1) : 0;   // +1 = self loop
        int x = v;
        #pragma unroll
        for (int o = 1; o < 32; o <<= 1) {
            int y = __shfl_up_sync(0xFFFFFFFFu, x, o);
            if (lane >= o) x += y;
        }
        if (lane == 31) warpsum[wid] = x;
        __syncthreads();
        if (wid == 0) {
            int s = warpsum[lane];
            #pragma unroll
            for (int o = 1; o < 32; o <<= 1) {
                int y = __shfl_up_sync(0xFFFFFFFFu, s, o);
                if (lane >= o) s += y;
            }
            warpsum[lane] = s;
        }
        __syncthreads();
        int woff = wid ? warpsum[wid - 1] : 0;
        int excl = carry_s + woff + x - v;
        if (i < NN) {
            g_off[i] = excl;
            g_cur[i] = excl + 1;     // slot 0 = self loop
            g_csr[excl] = i;
        }
        int total = warpsum[31];
        __syncthreads();
        if (tid == 0) carry_s += total;
        __syncthreads();
    }
    if (threadIdx.x == 0) g_off[NN] = carry_s;
}

__global__ void fill_csr_kernel(const int* __restrict__ ei) {
    int idx = blockIdx.x * blockDim.x + threadIdx.x;
    if (idx < EE) {
        int s = ei[idx];
        int d = ei[EE + idx];
        int pos = atomicAdd(&g_cur[d], 1);
        g_csr[pos] = s;
    }
}

// ---------------- fp16 GEMM (cp.async pipeline, BK=64) + fused logits ----------
// C[M,ND] = A[M,KD] @ B[KD,ND]; also asrc[n,h], adst[n,h] in-epilogue.
// mma.sync.m16n8k16 f16 (f32 accum). BM=128, BN=128, BK=64, 256 threads
// (8 warps, 4x2, 32x64 warp tile). ST-stage cp.async pipeline, 1 sync/iter.

__device__ __forceinline__ unsigned smaddr(const void* p) {
    return (unsigned)__cvta_generic_to_shared(p);
}

__device__ __forceinline__ void cp_async16(unsigned dst, const void* src, bool valid) {
    int sz = valid ? 16 : 0;   // src-size 0 -> zero-fill 16B
    asm volatile("cp.async.cg.shared.global [%0], [%1], 16, %2;"
                 :: "r"(dst), "l"(src), "r"(sz));
}

template<int KD, int ND, int CH>
__global__ __launch_bounds__(256)
void h16_gemm_kernel(int M, const __half* __restrict__ A,
                     const __half* __restrict__ B, __half* __restrict__ C,
                     const float* __restrict__ att_s, const float* __restrict__ att_d,
                     float* __restrict__ asrc, float* __restrict__ adst) {
    constexpr int BM = 128, BN = 128, BK = 64;
    constexpr int KT = KD / BK;
    constexpr int ST = (KT >= 3) ? 3 : ((KT >= 2) ? 2 : 1);
    constexpr int WG = (ST >= 2) ? ST - 2 : 0;
    constexpr int AS_STRIDE = BK + 8;              // 144B rows (9*16B, odd)
    constexpr int BS_STRIDE = BN + 8;              // 272B rows (17*16B, odd)

    extern __shared__ __align__(16) char smem_raw[];
    typedef __half (*AsPtr)[BM][AS_STRIDE];
    typedef __half (*BsPtr)[BK][BS_STRIDE];
    AsPtr As = reinterpret_cast<AsPtr>(smem_raw);
    BsPtr Bs = reinterpret_cast<BsPtr>(smem_raw + (size_t)ST * BM * AS_STRIDE * sizeof(__half));

    const int tid  = threadIdx.x;
    const int lane = tid & 31;
    const int warp = tid >> 5;
    const int wm = warp >> 1;              // 0..3
    const int wn = warp & 1;               // 0..1
    const int rowBase = blockIdx.y * BM;
    const int colBase = blockIdx.x * BN;

    float c[2][8][4];
    #pragma unroll
    for (int mf = 0; mf < 2; mf++)
        #pragma unroll
        for (int nf = 0; nf < 8; nf++)
            #pragma unroll
            for (int i = 0; i < 4; i++) c[mf][nf][i] = 0.f;

    const int arA = tid >> 3;              // 0..31 (+32*i)
    const int acA = (tid & 7) * 8;         // 0..56
    const int brB = tid >> 4;              // 0..15 (+16*i)
    const int bcB = (tid & 15) * 8;        // 0..120
    const int g  = lane >> 2;
    const int tg = lane & 3;

    auto issue = [&](int it) {             // stage `it` -> buffer it%ST; 1 commit group
        const int buf = it % ST;
        const int k0 = it * BK;
        #pragma unroll
        for (int i = 0; i < 4; i++) {
            int r = rowBase + arA + i * 32;
            cp_async16(smaddr(&As[buf][arA + i * 32][acA]),
                       &A[(size_t)r * KD + k0 + acA], r < M);
        }
        #pragma unroll
        for (int j = 0; j < 4; j++)
            cp_async16(smaddr(&Bs[buf][brB + j * 16][bcB]),
                       &B[(size_t)(k0 + brB + j * 16) * ND + colBase + bcB], true);
        asm volatile("cp.async.commit_group;");
    };

    auto compute = [&](int buf) {
        #pragma unroll
        for (int ks = 0; ks < BK / 16; ks++) {
            unsigned a[2][4], b[8][2];
            #pragma unroll
            for (int mf = 0; mf < 2; mf++) {
                unsigned ad = smaddr(&As[buf][wm * 32 + mf * 16 + (lane & 15)]
                                            [ks * 16 + ((lane >> 4) & 1) * 8]);
                asm volatile(
                    "ldmatrix.sync.aligned.m8n8.x4.shared.b16 {%0,%1,%2,%3}, [%4];"
                    : "=r"(a[mf][0]), "=r"(a[mf][1]), "=r"(a[mf][2]), "=r"(a[mf][3])
                    : "r"(ad));
            }
            #pragma unroll
            for (int nq = 0; nq < 4; nq++) {
                unsigned ad = smaddr(&Bs[buf][ks * 16 + (lane & 15)]
                                            [wn * 64 + nq * 16 + ((lane >> 4) & 1) * 8]);
                asm volatile(
                    "ldmatrix.sync.aligned.m8n8.x4.trans.shared.b16 {%0,%1,%2,%3}, [%4];"
                    : "=r"(b[nq * 2][0]), "=r"(b[nq * 2][1]),
                      "=r"(b[nq * 2 + 1][0]), "=r"(b[nq * 2 + 1][1])
                    : "r"(ad));
            }
            #pragma unroll
            for (int mf = 0; mf < 2; mf++)
                #pragma unroll
                for (int nf = 0; nf < 8; nf++)
                    asm volatile(
                        "mma.sync.aligned.m16n8k16.row.col.f32.f16.f16.f32 "
                        "{%0,%1,%2,%3}, {%4,%5,%6,%7}, {%8,%9}, {%0,%1,%2,%3};"
                        : "+f"(c[mf][nf][0]), "+f"(c[mf][nf][1]),
                          "+f"(c[mf][nf][2]), "+f"(c[mf][nf][3])
                        : "r"(a[mf][0]), "r"(a[mf][1]), "r"(a[mf][2]), "r"(a[mf][3]),
                          "r"(b[nf][0]), "r"(b[nf][1]));
        }
    };

    // prologue: for ST>=2 issue stages 0..ST-2; for ST==1 issue stage 0
    constexpr int PRO = (ST >= 2) ? ST - 1 : 1;
    #pragma unroll
    for (int s = 0; s < PRO; s++) issue(s);

    #pragma unroll
    for (int it = 0; it < KT; it++) {
        asm volatile("cp.async.wait_group %0;" :: "n"(WG));   // stage it resident
        __syncthreads();                   // data visible + all warps done w/ old buf
        if (ST >= 2 && it + ST - 1 < KT) issue(it + ST - 1);
        compute(it % ST);
    }

    // ---- store C ----
    #pragma unroll
    for (int mf = 0; mf < 2; mf++) {
        #pragma unroll
        for (int nf = 0; nf < 8; nf++) {
            int col = colBase + wn * 64 + nf * 8 + tg * 2;
            int r0 = rowBase + wm * 32 + mf * 16 + g;
            if (r0 < M)
                *(half2*)&C[(size_t)r0 * ND + col] = __floats2half2_rn(c[mf][nf][0], c[mf][nf][1]);
            int r1 = r0 + 8;
            if (r1 < M)
                *(half2*)&C[(size_t)r1 * ND + col] = __floats2half2_rn(c[mf][nf][2], c[mf][nf][3]);
        }
    }

    // ---- fused attention logits ----
    constexpr int NFH = CH / 8;            // nf per head (8 or 4)
    constexpr int NHW = 8 / NFH;           // heads per warp tile (1 or 2)
    const int headBase = (colBase + wn * 64) / CH;
    float asv[8][2], adv[8][2];
    #pragma unroll
    for (int nf = 0; nf < 8; nf++) {
        int hl  = nf / NFH;
        int cih = (nf % NFH) * 8 + tg * 2;
        int idx = (headBase + hl) * CH + cih;
        asv[nf][0] = att_s[idx];     asv[nf][1] = att_s[idx + 1];
        adv[nf][0] = att_d[idx];     adv[nf][1] = att_d[idx + 1];
    }
    #pragma unroll
    for (int mf = 0; mf < 2; mf++) {
        float ps0[NHW], pd0[NHW], ps1[NHW], pd1[NHW];
        #pragma unroll
        for (int hl = 0; hl < NHW; hl++) { ps0[hl] = pd0[hl] = ps1[hl] = pd1[hl] = 0.f; }
        #pragma unroll
        for (int nf = 0; nf < 8; nf++) {
            int hl = nf / NFH;
            ps0[hl] += c[mf][nf][0] * asv[nf][0] + c[mf][nf][1] * asv[nf][1];
            pd0[hl] += c[mf][nf][0] * adv[nf][0] + c[mf][nf][1] * adv[nf][1];
            ps1[hl] += c[mf][nf][2] * asv[nf][0] + c[mf][nf][3] * asv[nf][1];
            pd1[hl] += c[mf][nf][2] * adv[nf][0] + c[mf][nf][3] * adv[nf][1];
        }
        int r0 = rowBase + wm * 32 + mf * 16 + g;
        int r1 = r0 + 8;
        #pragma unroll
        for (int hl = 0; hl < NHW; hl++) {
            #pragma unroll
            for (int o = 1; o <= 2; o <<= 1) {
                ps0[hl] += __shfl_xor_sync(0xFFFFFFFFu, ps0[hl], o);
                pd0[hl] += __shfl_xor_sync(0xFFFFFFFFu, pd0[hl], o);
                ps1[hl] += __shfl_xor_sync(0xFFFFFFFFu, ps1[hl], o);
                pd1[hl] += __shfl_xor_sync(0xFFFFFFFFu, pd1[hl], o);
            }
            if (tg == 0) {
                int hg = headBase + hl;
                if (r0 < M) { asrc[r0 * 8 + hg] = ps0[hl]; adst[r0 * 8 + hg] = pd0[hl]; }
                if (r1 < M) { asrc[r1 * 8 + hg] = ps1[hl]; adst[r1 * 8 + hg] = pd1[hl]; }
            }
        }
    }
}

// smem bytes for the pipeline (host-side mirror of kernel constants)
constexpr int gemm_smem_bytes(int KT) {
    int st = (KT >= 3) ? 3 : ((KT >= 2) ? 2 : 1);
    return st * (128 * (64 + 8) + 64 * (128 + 8)) * (int)sizeof(__half);
}

// ---------------- GAT aggregation: single-pass unnormalized softmax ----------------
template<int CH, typename OutT>
__global__ __launch_bounds__(256)
void gat_aggregate_kernel(const __half* __restrict__ h,
                          const float* __restrict__ asrc,
                          const float* __restrict__ adst,
                          const float* __restrict__ bias,
                          OutT* __restrict__ out,
                          int do_relu) {
    constexpr int NT   = 256;
    constexpr int CK   = 256;              // chunk size
    constexpr int TPE  = CH;               // threads per edge (row = CH uint4)
    constexpr int EPB  = NT / TPE;         // edges in parallel (4 or 8)
    constexpr int TPH  = CH / 8;           // threads per head (8 or 4)
    const int d = blockIdx.x;
    const int t = threadIdx.x;
    const int start = g_off[d];
    const int deg = g_off[d + 1] - start;

    __shared__ float sm_adst[8], sm_is[8];
    __shared__ int   s_src[CK];
    __shared__ float s_w[CK * 8];
    __shared__ float s_dp[NT];
    __shared__ float s_red[EPB][8][CH];

    if (t < 8) sm_adst[t] = adst[d * 8 + t];
    __syncthreads();

    const int sub = t / TPE;               // which edge of the group
    const int rr  = t % TPE;
    const int hh  = rr / TPH;              // head
    const int co  = rr % TPH;              // uint4 index within head (8 channels)
    const uint4* __restrict__ h8p = (const uint4*)h;
    float acc[8] = {0.f, 0.f, 0.f, 0.f, 0.f, 0.f, 0.f, 0.f};
    float denp = 0.f;

    for (int base = 0; base < deg; base += CK) {
        const int cnt = min(CK, deg - base);
        if (t < cnt) s_src[t] = g_csr[start + base + t];
        __syncthreads();
        for (int idx = t; idx < cnt * 8; idx += NT) {
            int j = idx >> 3, h2 = idx & 7;
            int s = s_src[j];
            float e = asrc[s * 8 + h2] + sm_adst[h2];
            e = (e > 0.f) ? e : NEG_SLOPE * e;
            float w = __expf(e);
            s_w[idx] = w;
            denp += w;
        }
        __syncthreads();
        #pragma unroll 4
        for (int j = sub; j < cnt; j += EPB) {
            float w = s_w[j * 8 + hh];
            uint4 raw = h8p[(size_t)s_src[j] * CH + hh * TPH + co];
            float2 v0 = __half22float2(*(const half2*)&raw.x);
            float2 v1 = __half22float2(*(const half2*)&raw.y);
            float2 v2 = __half22float2(*(const half2*)&raw.z);
            float2 v3 = __half22float2(*(const half2*)&raw.w);
            acc[0] = fmaf(w, v0.x, acc[0]);
            acc[1] = fmaf(w, v0.y, acc[1]);
            acc[2] = fmaf(w, v1.x, acc[2]);
            acc[3] = fmaf(w, v1.y, acc[3]);
            acc[4] = fmaf(w, v2.x, acc[4]);
            acc[5] = fmaf(w, v2.y, acc[5]);
            acc[6] = fmaf(w, v3.x, acc[6]);
            acc[7] = fmaf(w, v3.y, acc[7]);
        }
        __syncthreads();
    }

    s_dp[t] = denp;
    __syncthreads();
    if (t < 8) {
        float tot = 0.f;
        #pragma unroll
        for (int k = t; k < NT; k += 8) tot += s_dp[k];
        sm_is[t] = 1.0f / tot;
    }
    __syncthreads();

    const float is = sm_is[hh];
    *(float4*)&s_red[sub][hh][co * 8]     = make_float4(acc[0] * is, acc[1] * is,
                                                        acc[2] * is, acc[3] * is);
    *(float4*)&s_red[sub][hh][co * 8 + 4] = make_float4(acc[4] * is, acc[5] * is,
                                                        acc[6] * is, acc[7] * is);
    __syncthreads();
    if (t < CH) {
        float v = 0.f;
        #pragma unroll
        for (int sb = 0; sb < EPB; sb++)
            #pragma unroll
            for (int k = 0; k < 8; k++) v += s_red[sb][k][t];
        v = v * 0.125f + bias[t];
        if (do_relu) v = fmaxf(v, 0.f);
        if constexpr (sizeof(OutT) == 2)
            out[(size_t)d * CH + t] = __float2half(v);
        else
            out[(size_t)d * CH + t] = v;
    }
}

// ---------------- launch ----------------
extern "C" void kernel_launch(void* const* d_in, const int* in_sizes, int n_in,
                              void* d_out, int out_size) {
    const float* x    = (const float*)d_in[0];
    const int*   ei   = (const int*)  d_in[1];
    const float* W1   = (const float*)d_in[2];
    const float* as1  = (const float*)d_in[3];
    const float* ad1  = (const float*)d_in[4];
    const float* b1   = (const float*)d_in[5];
    const float* W2   = (const float*)d_in[6];
    const float* as2  = (const float*)d_in[7];
    const float* ad2  = (const float*)d_in[8];
    const float* b2   = (const float*)d_in[9];
    float* out = (float*)d_out;

    __half *p_xh, *p_W1h, *p_W2h, *p_h1, *p_hmid, *p_h2;
    float *p_as1, *p_ad1, *p_as2, *p_ad2;
    int *p_deg;
    cudaGetSymbolAddress((void**)&p_xh,   g_xh);
    cudaGetSymbolAddress((void**)&p_W1h,  g_W1h);
    cudaGetSymbolAddress((void**)&p_W2h,  g_W2h);
    cudaGetSymbolAddress((void**)&p_h1,   g_h1);
    cudaGetSymbolAddress((void**)&p_hmid, g_hmid);
    cudaGetSymbolAddress((void**)&p_h2,   g_h2);
    cudaGetSymbolAddress((void**)&p_as1,  g_as1);
    cudaGetSymbolAddress((void**)&p_ad1,  g_ad1);
    cudaGetSymbolAddress((void**)&p_as2,  g_as2);
    cudaGetSymbolAddress((void**)&p_ad2,  g_ad2);
    cudaGetSymbolAddress((void**)&p_deg,  g_deg);

    // one-time side stream + events (no device memory; created on first call,
    // which is the non-captured correctness run)
    static cudaStream_t s2 = nullptr;
    static cudaEvent_t evFork = nullptr, evJoin = nullptr;
    if (s2 == nullptr) {
        cudaStreamCreateWithFlags(&s2, cudaStreamNonBlocking);
        cudaEventCreateWithFlags(&evFork, cudaEventDisableTiming);
        cudaEventCreateWithFlags(&evJoin, cudaEventDisableTiming);
    }

    constexpr int SM1 = gemm_smem_bytes(INF_C / 64);   // KT=4 -> 3 stages
    constexpr int SM2 = gemm_smem_bytes(HF1 / 64);     // KT=1 -> 1 stage
    cudaFuncSetAttribute(h16_gemm_kernel<INF_C, HEADS * HF1, HF1>,
                         cudaFuncAttributeMaxDynamicSharedMemorySize, SM1);
    cudaFuncSetAttribute(h16_gemm_kernel<HF1, HEADS * OUT2, OUT2>,
                         cudaFuncAttributeMaxDynamicSharedMemorySize, SM2);

    // ---- fork: side chain = conversions -> GEMM1+logits1 ----
    cudaEventRecord(evFork, 0);
    cudaStreamWaitEvent(s2, evFork, 0);
    {
        constexpr int NCONV = NN * INF_C / 4 + INF_C * HEADS * HF1 / 4
                            + HF1 * HEADS * OUT2 / 4;
        conv_kernel<<<(NCONV + 255) / 256, 256, 0, s2>>>(x, W1, W2);
        dim3 grid((HEADS * HF1) / 128, (NN + 127) / 128);
        h16_gemm_kernel<INF_C, HEADS * HF1, HF1><<<grid, 256, SM1, s2>>>(
            NN, p_xh, p_W1h, p_h1, as1, ad1, p_as1, p_ad1);
    }
    cudaEventRecord(evJoin, s2);

    // ---- main chain: CSR build ----
    cudaMemsetAsync(p_deg, 0, NN * sizeof(int));
    count_deg_kernel<<<(EE + 255) / 256, 256>>>(ei);
    scan_kernel<<<1, 1024>>>();
    fill_csr_kernel<<<(EE + 255) / 256, 256>>>(ei);

    // ---- join, then aggregation 1 ----
    cudaStreamWaitEvent(0, evJoin, 0);
    gat_aggregate_kernel<HF1, __half><<<NN, 256>>>(p_h1, p_as1, p_ad1, b1, p_hmid, 1);

    // GEMM2 + logits2
    {
        dim3 grid((HEADS * OUT2) / 128, (NN + 127) / 128);
        h16_gemm_kernel<HF1, HEADS * OUT2, OUT2><<<grid, 256, SM2>>>(
            NN, p_hmid, p_W2h, p_h2, as2, ad2, p_as2, p_ad2);
    }
    // aggregation 2
    gat_aggregate_kernel<OUT2, float><<<NN, 256>>>(p_h2, p_as2, p_ad2, b2, out, 0);
}

// round 15
// speedup vs baseline: 1.0958x; 1.0958x over previous
#include <cuda_runtime.h>
#include <cuda_fp16.h>
#include <math_constants.h>

// Problem constants (fixed by the reference)
#define NN     20000
#define EE     640000
#define ETOT   (EE + NN)      // edges + self loops
#define INF_C  256
#define HEADS  8
#define HF1    64
#define OUT2   32
#define NEG_SLOPE 0.2f
#define NB     ((NN + 1023) / 1024)   // 20 scan blocks

// ---------------- static scratch (no allocations allowed) ----------------
__device__ __half g_xh  [NN * INF_C];         // x in fp16
__device__ __half g_W1h [INF_C * HEADS * HF1];
__device__ __half g_W2h [HF1 * HEADS * OUT2];
__device__ __half g_h1  [NN * HEADS * HF1];   // layer1 projected features (fp16)
__device__ __half g_hmid[NN * HF1];           // layer1 output (fp16, feeds GEMM2)
__device__ __half g_h2  [NN * HEADS * OUT2];  // layer2 projected features (fp16)
__device__ __align__(16) float g_as1 [NN * HEADS];
__device__ __align__(16) float g_ad1 [NN * HEADS];
__device__ __align__(16) float g_as2 [NN * HEADS];
__device__ __align__(16) float g_ad2 [NN * HEADS];
__device__ int   g_deg [NN];
__device__ int   g_off [NN + 1];
__device__ int   g_cur [NN];
__device__ int   g_bsum[NB];
__device__ int   g_csr [ETOT];               // src node of each edge, grouped by dst

// ---------------- conversions (stream 2) ----------------
__device__ __forceinline__ void cvt4(const float* src, __half* dst, int i) {
    float4 v = ((const float4*)src)[i];
    ((half2*)dst)[2 * i]     = __floats2half2_rn(v.x, v.y);
    ((half2*)dst)[2 * i + 1] = __floats2half2_rn(v.z, v.w);
}

__global__ void conv_kernel(const float* __restrict__ x,
                            const float* __restrict__ W1,
                            const float* __restrict__ W2) {
    constexpr int NX  = NN * INF_C / 4;
    constexpr int NW1 = INF_C * HEADS * HF1 / 4;
    constexpr int NW2 = HF1 * HEADS * OUT2 / 4;
    int i = blockIdx.x * blockDim.x + threadIdx.x;
    if (i < NX)                   cvt4(x,  g_xh,  i);
    else if (i < NX + NW1)        cvt4(W1, g_W1h, i - NX);
    else if (i < NX + NW1 + NW2)  cvt4(W2, g_W2h, i - NX - NW1);
}

// ---------------- CSR build (stream 0) ----------------
__global__ void count_deg_kernel(const int* __restrict__ ei) {
    int e = blockIdx.x * blockDim.x + threadIdx.x;
    if (e < EE) atomicAdd(&g_deg[ei[EE + e]], 1);
}

// phase 1: per-block exclusive scan of (deg+1); block totals to g_bsum
__global__ void scan1_kernel() {
    __shared__ int warpsum[32];
    const int tid = threadIdx.x, lane = tid & 31, wid = tid >> 5;
    const int i = blockIdx.x * 1024 + tid;
    int v = (i < NN) ? (g_deg[i] + 1) : 0;   // +1 = self loop
    int x = v;
    #pragma unroll
    for (int o = 1; o < 32; o <<= 1) {
        int y = __shfl_up_sync(0xFFFFFFFFu, x, o);
        if (lane >= o) x += y;
    }
    if (lane == 31) warpsum[wid] = x;
    __syncthreads();
    if (wid == 0) {
        int s = warpsum[lane];
        #pragma unroll
        for (int o = 1; o < 32; o <<= 1) {
            int y = __shfl_up_sync(0xFFFFFFFFu, s, o);
            if (lane >= o) s += y;
        }
        warpsum[lane] = s;
    }
    __syncthreads();
    int woff = wid ? warpsum[wid - 1] : 0;
    if (i < NN) g_off[i] = woff + x - v;       // block-local exclusive
    if (tid == 1023) g_bsum[blockIdx.x] = woff + x;   // block total
}

// phase 2: add block prefix; init cursor (slot 0 = self loop); write self loops
__global__ void scan2_kernel() {
    __shared__ int s_prefix, s_total;
    const int tid = threadIdx.x, lane = tid & 31;
    if (tid < 32) {
        int v = (lane < NB) ? g_bsum[lane] : 0;
        int x = v;
        #pragma unroll
        for (int o = 1; o < 32; o <<= 1) {
            int y = __shfl_up_sync(0xFFFFFFFFu, x, o);
            if (lane >= o) x += y;
        }
        if (lane == (int)blockIdx.x) s_prefix = x - v;   // exclusive prefix of this block
        if (lane == NB - 1) s_total = x;
    }
    __syncthreads();
    const int i = blockIdx.x * 1024 + tid;
    if (i < NN) {
        int excl = g_off[i] + s_prefix;
        g_off[i] = excl;
        g_cur[i] = excl + 1;     // slot 0 = self loop
        g_csr[excl] = i;
    }
    if (blockIdx.x == 0 && tid == 0) g_off[NN] = s_total;
}

__global__ void fill_csr_kernel(const int* __restrict__ ei) {
    int idx = blockIdx.x * blockDim.x + threadIdx.x;
    if (idx < EE) {
        int s = ei[idx];
        int d = ei[EE + idx];
        int pos = atomicAdd(&g_cur[d], 1);
        g_csr[pos] = s;
    }
}

// ---------------- fp16 GEMM (cp.async pipeline, BK=64) + fused logits ----------
// C[M,ND] = A[M,KD] @ B[KD,ND]; also asrc[n,h], adst[n,h] in-epilogue.
// mma.sync.m16n8k16 f16 (f32 accum). BM=128, BN=128, BK=64, 256 threads
// (8 warps, 4x2, 32x64 warp tile). ST-stage cp.async pipeline, 1 sync/iter.

__device__ __forceinline__ unsigned smaddr(const void* p) {
    return (unsigned)__cvta_generic_to_shared(p);
}

__device__ __forceinline__ void cp_async16(unsigned dst, const void* src, bool valid) {
    int sz = valid ? 16 : 0;   // src-size 0 -> zero-fill 16B
    asm volatile("cp.async.cg.shared.global [%0], [%1], 16, %2;"
                 :: "r"(dst), "l"(src), "r"(sz));
}

template<int KD, int ND, int CH>
__global__ __launch_bounds__(256)
void h16_gemm_kernel(int M, const __half* __restrict__ A,
                     const __half* __restrict__ B, __half* __restrict__ C,
                     const float* __restrict__ att_s, const float* __restrict__ att_d,
                     float* __restrict__ asrc, float* __restrict__ adst) {
    constexpr int BM = 128, BN = 128, BK = 64;
    constexpr int KT = KD / BK;
    constexpr int ST = (KT >= 3) ? 3 : ((KT >= 2) ? 2 : 1);
    constexpr int WG = (ST >= 2) ? ST - 2 : 0;
    constexpr int AS_STRIDE = BK + 8;              // 144B rows (9*16B, odd)
    constexpr int BS_STRIDE = BN + 8;              // 272B rows (17*16B, odd)

    extern __shared__ __align__(16) char smem_raw[];
    typedef __half (*AsPtr)[BM][AS_STRIDE];
    typedef __half (*BsPtr)[BK][BS_STRIDE];
    AsPtr As = reinterpret_cast<AsPtr>(smem_raw);
    BsPtr Bs = reinterpret_cast<BsPtr>(smem_raw + (size_t)ST * BM * AS_STRIDE * sizeof(__half));

    const int tid  = threadIdx.x;
    const int lane = tid & 31;
    const int warp = tid >> 5;
    const int wm = warp >> 1;              // 0..3
    const int wn = warp & 1;               // 0..1
    const int rowBase = blockIdx.y * BM;
    const int colBase = blockIdx.x * BN;

    float c[2][8][4];
    #pragma unroll
    for (int mf = 0; mf < 2; mf++)
        #pragma unroll
        for (int nf = 0; nf < 8; nf++)
            #pragma unroll
            for (int i = 0; i < 4; i++) c[mf][nf][i] = 0.f;

    const int arA = tid >> 3;              // 0..31 (+32*i)
    const int acA = (tid & 7) * 8;         // 0..56
    const int brB = tid >> 4;              // 0..15 (+16*i)
    const int bcB = (tid & 15) * 8;        // 0..120
    const int g  = lane >> 2;
    const int tg = lane & 3;

    auto issue = [&](int it) {             // stage `it` -> buffer it%ST; 1 commit group
        const int buf = it % ST;
        const int k0 = it * BK;
        #pragma unroll
        for (int i = 0; i < 4; i++) {
            int r = rowBase + arA + i * 32;
            cp_async16(smaddr(&As[buf][arA + i * 32][acA]),
                       &A[(size_t)r * KD + k0 + acA], r < M);
        }
        #pragma unroll
        for (int j = 0; j < 4; j++)
            cp_async16(smaddr(&Bs[buf][brB + j * 16][bcB]),
                       &B[(size_t)(k0 + brB + j * 16) * ND + colBase + bcB], true);
        asm volatile("cp.async.commit_group;");
    };

    auto compute = [&](int buf) {
        #pragma unroll
        for (int ks = 0; ks < BK / 16; ks++) {
            unsigned a[2][4], b[8][2];
            #pragma unroll
            for (int mf = 0; mf < 2; mf++) {
                unsigned ad = smaddr(&As[buf][wm * 32 + mf * 16 + (lane & 15)]
                                            [ks * 16 + ((lane >> 4) & 1) * 8]);
                asm volatile(
                    "ldmatrix.sync.aligned.m8n8.x4.shared.b16 {%0,%1,%2,%3}, [%4];"
                    : "=r"(a[mf][0]), "=r"(a[mf][1]), "=r"(a[mf][2]), "=r"(a[mf][3])
                    : "r"(ad));
            }
            #pragma unroll
            for (int nq = 0; nq < 4; nq++) {
                unsigned ad = smaddr(&Bs[buf][ks * 16 + (lane & 15)]
                                            [wn * 64 + nq * 16 + ((lane >> 4) & 1) * 8]);
                asm volatile(
                    "ldmatrix.sync.aligned.m8n8.x4.trans.shared.b16 {%0,%1,%2,%3}, [%4];"
                    : "=r"(b[nq * 2][0]), "=r"(b[nq * 2][1]),
                      "=r"(b[nq * 2 + 1][0]), "=r"(b[nq * 2 + 1][1])
                    : "r"(ad));
            }
            #pragma unroll
            for (int mf = 0; mf < 2; mf++)
                #pragma unroll
                for (int nf = 0; nf < 8; nf++)
                    asm volatile(
                        "mma.sync.aligned.m16n8k16.row.col.f32.f16.f16.f32 "
                        "{%0,%1,%2,%3}, {%4,%5,%6,%7}, {%8,%9}, {%0,%1,%2,%3};"
                        : "+f"(c[mf][nf][0]), "+f"(c[mf][nf][1]),
                          "+f"(c[mf][nf][2]), "+f"(c[mf][nf][3])
                        : "r"(a[mf][0]), "r"(a[mf][1]), "r"(a[mf][2]), "r"(a[mf][3]),
                          "r"(b[nf][0]), "r"(b[nf][1]));
        }
    };

    // prologue: for ST>=2 issue stages 0..ST-2; for ST==1 issue stage 0
    constexpr int PRO = (ST >= 2) ? ST - 1 : 1;
    #pragma unroll
    for (int s = 0; s < PRO; s++) issue(s);

    #pragma unroll
    for (int it = 0; it < KT; it++) {
        asm volatile("cp.async.wait_group %0;" :: "n"(WG));   // stage it resident
        __syncthreads();                   // data visible + all warps done w/ old buf
        if (ST >= 2 && it + ST - 1 < KT) issue(it + ST - 1);
        compute(it % ST);
    }

    // ---- store C ----
    #pragma unroll
    for (int mf = 0; mf < 2; mf++) {
        #pragma unroll
        for (int nf = 0; nf < 8; nf++) {
            int col = colBase + wn * 64 + nf * 8 + tg * 2;
            int r0 = rowBase + wm * 32 + mf * 16 + g;
            if (r0 < M)
                *(half2*)&C[(size_t)r0 * ND + col] = __floats2half2_rn(c[mf][nf][0], c[mf][nf][1]);
            int r1 = r0 + 8;
            if (r1 < M)
                *(half2*)&C[(size_t)r1 * ND + col] = __floats2half2_rn(c[mf][nf][2], c[mf][nf][3]);
        }
    }

    // ---- fused attention logits ----
    constexpr int NFH = CH / 8;            // nf per head (8 or 4)
    constexpr int NHW = 8 / NFH;           // heads per warp tile (1 or 2)
    const int headBase = (colBase + wn * 64) / CH;
    float asv[8][2], adv[8][2];
    #pragma unroll
    for (int nf = 0; nf < 8; nf++) {
        int hl  = nf / NFH;
        int cih = (nf % NFH) * 8 + tg * 2;
        int idx = (headBase + hl) * CH + cih;
        asv[nf][0] = att_s[idx];     asv[nf][1] = att_s[idx + 1];
        adv[nf][0] = att_d[idx];     adv[nf][1] = att_d[idx + 1];
    }
    #pragma unroll
    for (int mf = 0; mf < 2; mf++) {
        float ps0[NHW], pd0[NHW], ps1[NHW], pd1[NHW];
        #pragma unroll
        for (int hl = 0; hl < NHW; hl++) { ps0[hl] = pd0[hl] = ps1[hl] = pd1[hl] = 0.f; }
        #pragma unroll
        for (int nf = 0; nf < 8; nf++) {
            int hl = nf / NFH;
            ps0[hl] += c[mf][nf][0] * asv[nf][0] + c[mf][nf][1] * asv[nf][1];
            pd0[hl] += c[mf][nf][0] * adv[nf][0] + c[mf][nf][1] * adv[nf][1];
            ps1[hl] += c[mf][nf][2] * asv[nf][0] + c[mf][nf][3] * asv[nf][1];
            pd1[hl] += c[mf][nf][2] * adv[nf][0] + c[mf][nf][3] * adv[nf][1];
        }
        int r0 = rowBase + wm * 32 + mf * 16 + g;
        int r1 = r0 + 8;
        #pragma unroll
        for (int hl = 0; hl < NHW; hl++) {
            #pragma unroll
            for (int o = 1; o <= 2; o <<= 1) {
                ps0[hl] += __shfl_xor_sync(0xFFFFFFFFu, ps0[hl], o);
                pd0[hl] += __shfl_xor_sync(0xFFFFFFFFu, pd0[hl], o);
                ps1[hl] += __shfl_xor_sync(0xFFFFFFFFu, ps1[hl], o);
                pd1[hl] += __shfl_xor_sync(0xFFFFFFFFu, pd1[hl], o);
            }
            if (tg == 0) {
                int hg = headBase + hl;
                if (r0 < M) { asrc[r0 * 8 + hg] = ps0[hl]; adst[r0 * 8 + hg] = pd0[hl]; }
                if (r1 < M) { asrc[r1 * 8 + hg] = ps1[hl]; adst[r1 * 8 + hg] = pd1[hl]; }
            }
        }
    }
}

// smem bytes for the pipeline (host-side mirror of kernel constants)
constexpr int gemm_smem_bytes(int KT) {
    int st = (KT >= 3) ? 3 : ((KT >= 2) ? 2 : 1);
    return st * (128 * (64 + 8) + 64 * (128 + 8)) * (int)sizeof(__half);
}

// ---------------- GAT aggregation: single-pass unnormalized softmax ----------------
template<int CH, typename OutT>
__global__ __launch_bounds__(256)
void gat_aggregate_kernel(const __half* __restrict__ h,
                          const float* __restrict__ asrc,
                          const float* __restrict__ adst,
                          const float* __restrict__ bias,
                          OutT* __restrict__ out,
                          int do_relu) {
    constexpr int NT   = 256;
    constexpr int CK   = 256;              // chunk size
    constexpr int TPE  = CH;               // threads per edge (row = CH uint4)
    constexpr int EPB  = NT / TPE;         // edges in parallel (4 or 8)
    constexpr int TPH  = CH / 8;           // threads per head (8 or 4)
    const int d = blockIdx.x;
    const int t = threadIdx.x;
    const int start = g_off[d];
    const int deg = g_off[d + 1] - start;

    __shared__ float sm_adst[8], sm_is[8];
    __shared__ int   s_src[CK];
    __shared__ float s_w[CK * 8];
    __shared__ float s_dp[NT];
    __shared__ float s_red[EPB][8][CH];

    if (t < 8) sm_adst[t] = adst[d * 8 + t];
    __syncthreads();

    const int sub = t / TPE;               // which edge of the group
    const int rr  = t % TPE;
    const int hh  = rr / TPH;              // head
    const int co  = rr % TPH;              // uint4 index within head (8 channels)
    const uint4* __restrict__ h8p = (const uint4*)h;
    float acc[8] = {0.f, 0.f, 0.f, 0.f, 0.f, 0.f, 0.f, 0.f};
    float denp = 0.f;

    for (int base = 0; base < deg; base += CK) {
        const int cnt = min(CK, deg - base);
        if (t < cnt) s_src[t] = g_csr[start + base + t];
        __syncthreads();
        for (int idx = t; idx < cnt * 8; idx += NT) {
            int j = idx >> 3, h2 = idx & 7;
            int s = s_src[j];
            float e = asrc[s * 8 + h2] + sm_adst[h2];
            e = (e > 0.f) ? e : NEG_SLOPE * e;
            float w = __expf(e);
            s_w[idx] = w;
            denp += w;
        }
        __syncthreads();
        #pragma unroll 4
        for (int j = sub; j < cnt; j += EPB) {
            float w = s_w[j * 8 + hh];
            uint4 raw = h8p[(size_t)s_src[j] * CH + hh * TPH + co];
            float2 v0 = __half22float2(*(const half2*)&raw.x);
            float2 v1 = __half22float2(*(const half2*)&raw.y);
            float2 v2 = __half22float2(*(const half2*)&raw.z);
            float2 v3 = __half22float2(*(const half2*)&raw.w);
            acc[0] = fmaf(w, v0.x, acc[0]);
            acc[1] = fmaf(w, v0.y, acc[1]);
            acc[2] = fmaf(w, v1.x, acc[2]);
            acc[3] = fmaf(w, v1.y, acc[3]);
            acc[4] = fmaf(w, v2.x, acc[4]);
            acc[5] = fmaf(w, v2.y, acc[5]);
            acc[6] = fmaf(w, v3.x, acc[6]);
            acc[7] = fmaf(w, v3.y, acc[7]);
        }
        __syncthreads();
    }

    s_dp[t] = denp;
    __syncthreads();
    if (t < 8) {
        float tot = 0.f;
        #pragma unroll
        for (int k = t; k < NT; k += 8) tot += s_dp[k];
        sm_is[t] = 1.0f / tot;
    }
    __syncthreads();

    const float is = sm_is[hh];
    *(float4*)&s_red[sub][hh][co * 8]     = make_float4(acc[0] * is, acc[1] * is,
                                                        acc[2] * is, acc[3] * is);
    *(float4*)&s_red[sub][hh][co * 8 + 4] = make_float4(acc[4] * is, acc[5] * is,
                                                        acc[6] * is, acc[7] * is);
    __syncthreads();
    if (t < CH) {
        float v = 0.f;
        #pragma unroll
        for (int sb = 0; sb < EPB; sb++)
            #pragma unroll
            for (int k = 0; k < 8; k++) v += s_red[sb][k][t];
        v = v * 0.125f + bias[t];
        if (do_relu) v = fmaxf(v, 0.f);
        if constexpr (sizeof(OutT) == 2)
            out[(size_t)d * CH + t] = __float2half(v);
        else
            out[(size_t)d * CH + t] = v;
    }
}

// ---------------- launch ----------------
extern "C" void kernel_launch(void* const* d_in, const int* in_sizes, int n_in,
                              void* d_out, int out_size) {
    const float* x    = (const float*)d_in[0];
    const int*   ei   = (const int*)  d_in[1];
    const float* W1   = (const float*)d_in[2];
    const float* as1  = (const float*)d_in[3];
    const float* ad1  = (const float*)d_in[4];
    const float* b1   = (const float*)d_in[5];
    const float* W2   = (const float*)d_in[6];
    const float* as2  = (const float*)d_in[7];
    const float* ad2  = (const float*)d_in[8];
    const float* b2   = (const float*)d_in[9];
    float* out = (float*)d_out;

    __half *p_xh, *p_W1h, *p_W2h, *p_h1, *p_hmid, *p_h2;
    float *p_as1, *p_ad1, *p_as2, *p_ad2;
    int *p_deg;
    cudaGetSymbolAddress((void**)&p_xh,   g_xh);
    cudaGetSymbolAddress((void**)&p_W1h,  g_W1h);
    cudaGetSymbolAddress((void**)&p_W2h,  g_W2h);
    cudaGetSymbolAddress((void**)&p_h1,   g_h1);
    cudaGetSymbolAddress((void**)&p_hmid, g_hmid);
    cudaGetSymbolAddress((void**)&p_h2,   g_h2);
    cudaGetSymbolAddress((void**)&p_as1,  g_as1);
    cudaGetSymbolAddress((void**)&p_ad1,  g_ad1);
    cudaGetSymbolAddress((void**)&p_as2,  g_as2);
    cudaGetSymbolAddress((void**)&p_ad2,  g_ad2);
    cudaGetSymbolAddress((void**)&p_deg,  g_deg);

    // one-time side stream + events (no device memory; created on first call,
    // which is the non-captured correctness run)
    static cudaStream_t s2 = nullptr;
    static cudaEvent_t evFork = nullptr, evJoin = nullptr;
    if (s2 == nullptr) {
        cudaStreamCreateWithFlags(&s2, cudaStreamNonBlocking);
        cudaEventCreateWithFlags(&evFork, cudaEventDisableTiming);
        cudaEventCreateWithFlags(&evJoin, cudaEventDisableTiming);
    }

    constexpr int SM1 = gemm_smem_bytes(INF_C / 64);   // KT=4 -> 3 stages
    constexpr int SM2 = gemm_smem_bytes(HF1 / 64);     // KT=1 -> 1 stage
    cudaFuncSetAttribute(h16_gemm_kernel<INF_C, HEADS * HF1, HF1>,
                         cudaFuncAttributeMaxDynamicSharedMemorySize, SM1);
    cudaFuncSetAttribute(h16_gemm_kernel<HF1, HEADS * OUT2, OUT2>,
                         cudaFuncAttributeMaxDynamicSharedMemorySize, SM2);

    // ---- fork: side chain = conversions -> GEMM1+logits1 ----
    cudaEventRecord(evFork, 0);
    cudaStreamWaitEvent(s2, evFork, 0);
    {
        constexpr int NCONV = NN * INF_C / 4 + INF_C * HEADS * HF1 / 4
                            + HF1 * HEADS * OUT2 / 4;
        conv_kernel<<<(NCONV + 255) / 256, 256, 0, s2>>>(x, W1, W2);
        dim3 grid((HEADS * HF1) / 128, (NN + 127) / 128);
        h16_gemm_kernel<INF_C, HEADS * HF1, HF1><<<grid, 256, SM1, s2>>>(
            NN, p_xh, p_W1h, p_h1, as1, ad1, p_as1, p_ad1);
    }
    cudaEventRecord(evJoin, s2);

    // ---- main chain: CSR build (parallel 2-phase scan) ----
    cudaMemsetAsync(p_deg, 0, NN * sizeof(int));
    count_deg_kernel<<<(EE + 255) / 256, 256>>>(ei);
    scan1_kernel<<<NB, 1024>>>();
    scan2_kernel<<<NB, 1024>>>();
    fill_csr_kernel<<<(EE + 255) / 256, 256>>>(ei);

    // ---- join, then aggregation 1 ----
    cudaStreamWaitEvent(0, evJoin, 0);
    gat_aggregate_kernel<HF1, __half><<<NN, 256>>>(p_h1, p_as1, p_ad1, b1, p_hmid, 1);

    // GEMM2 + logits2
    {
        dim3 grid((HEADS * OUT2) / 128, (NN + 127) / 128);
        h16_gemm_kernel<HF1, HEADS * OUT2, OUT2><<<grid, 256, SM2>>>(
            NN, p_hmid, p_W2h, p_h2, as2, ad2, p_as2, p_ad2);
    }
    // aggregation 2
    gat_aggregate_kernel<OUT2, float><<<NN, 256>>>(p_h2, p_as2, p_ad2, b2, out, 0);
}